// round 11
// baseline (speedup 1.0000x reference)
#include <cuda_runtime.h>
#include <cuda_fp16.h>
#include <cstdint>

#define N_NODES 100000
#define N_EDGES 3200000
#define F_IN    512
#define F_H     128
#define F_OUT   40
#define F_PAD   64          // padded row length in halves (128 B rows)
#define K_ITERS 20
#define ALPHA   0.1f

#define SCAN_B  512
#define NBLK    ((N_NODES + SCAN_B - 1) / SCAN_B)   // 196

// ---------------- scratch (device globals; no runtime allocation) ----------
__device__ __half   g_h1[(size_t)N_NODES * F_H];
__device__ __half   g_W1h[(size_t)F_H * F_IN];
__device__ __half   g_W1l[(size_t)F_H * F_IN];
__device__ __half   g_W2Th[(size_t)F_OUT * F_H];
__device__ __half   g_W2Tl[(size_t)F_OUT * F_H];
__device__ __half   g_h0h[(size_t)N_NODES * F_PAD];   // padded 128B rows
__device__ __half   g_zhA[(size_t)N_NODES * F_PAD];
__device__ __half   g_zhB[(size_t)N_NODES * F_PAD];
__device__ int      g_cnt[N_NODES];
__device__ int      g_offs[N_NODES + 1];
__device__ int      g_cursor[N_NODES];
__device__ int      g_bsum[NBLK];
__device__ int      g_bsum2[NBLK];
__device__ float    g_dinv[N_NODES];
__device__ float    g_selfc[N_NODES];
__device__ uint32_t g_csr[N_EDGES];     // idx(17b)<<15 | half_bits(w)&0x7FFF

// ---------------- helpers ----------------------------------------------------
__device__ __forceinline__ void cp16(uint32_t s, const void* g) {
    asm volatile("cp.async.cg.shared.global [%0], [%1], 16;" :: "r"(s), "l"(g));
}
__device__ __forceinline__ uint32_t smem_u32(const void* p) {
    uint32_t a;
    asm("{ .reg .u64 t; cvta.to.shared.u64 t, %1; cvt.u32.u64 %0, t; }" : "=r"(a) : "l"(p));
    return a;
}
__device__ __forceinline__ void mma_f16(float* c, const uint32_t* a, const uint32_t* b) {
    asm volatile(
        "mma.sync.aligned.m16n8k16.row.col.f32.f16.f16.f32 "
        "{%0,%1,%2,%3}, {%4,%5,%6,%7}, {%8,%9}, {%0,%1,%2,%3};"
        : "+f"(c[0]), "+f"(c[1]), "+f"(c[2]), "+f"(c[3])
        : "r"(a[0]), "r"(a[1]), "r"(a[2]), "r"(a[3]), "r"(b[0]), "r"(b[1]));
}
__device__ __forceinline__ float dec_w(uint32_t p) {
    return __half2float(__ushort_as_half((unsigned short)(p & 0x7FFFu)));
}

// ---------------- prep kernels ----------------------------------------------
__global__ void k_prep0(const float* __restrict__ W1, const float* __restrict__ W2) {
    int i = blockIdx.x * blockDim.x + threadIdx.x;
    if (i < F_IN * F_H) {
        int k = i >> 7, n = i & 127;
        float v = W1[i];
        __half h = __float2half_rn(v);
        g_W1h[(size_t)n * F_IN + k] = h;
        g_W1l[(size_t)n * F_IN + k] = __float2half_rn(v - __half2float(h));
    }
    if (i < F_H * F_OUT) {
        int k = i / F_OUT, n = i % F_OUT;
        float v = W2[i];
        __half h = __float2half_rn(v);
        g_W2Th[(size_t)n * F_H + k] = h;
        g_W2Tl[(size_t)n * F_H + k] = __float2half_rn(v - __half2float(h));
    }
    if (i < N_NODES) g_cnt[i] = 0;
}
__global__ void k_count(const int* __restrict__ ei) {
    int e = blockIdx.x * blockDim.x + threadIdx.x;
    if (e < N_EDGES) atomicAdd(&g_cnt[ei[N_EDGES + e]], 1);
}
__global__ void k_scan1() {
    __shared__ int s[SCAN_B];
    int i = blockIdx.x * SCAN_B + threadIdx.x;
    int v = (i < N_NODES) ? g_cnt[i] : 0;
    if (i < N_NODES) {
        float d = (float)(v + 1);
        float r = rsqrtf(d);
        g_dinv[i]  = r;
        g_selfc[i] = (1.0f - ALPHA) * r * r;
    }
    s[threadIdx.x] = v;
    __syncthreads();
#pragma unroll
    for (int off = 1; off < SCAN_B; off <<= 1) {
        int t = (threadIdx.x >= off) ? s[threadIdx.x - off] : 0;
        __syncthreads();
        s[threadIdx.x] += t;
        __syncthreads();
    }
    if (i < N_NODES) g_offs[i] = s[threadIdx.x] - v;
    if (threadIdx.x == SCAN_B - 1) g_bsum[blockIdx.x] = s[SCAN_B - 1];
}
__global__ void k_scan2() {
    __shared__ int s[256];
    int t = threadIdx.x;
    int v = (t < NBLK) ? g_bsum[t] : 0;
    s[t] = v;
    __syncthreads();
#pragma unroll
    for (int off = 1; off < 256; off <<= 1) {
        int u = (t >= off) ? s[t - off] : 0;
        __syncthreads();
        s[t] += u;
        __syncthreads();
    }
    if (t < NBLK) g_bsum2[t] = s[t] - v;
    if (t == 0) g_offs[N_NODES] = s[255];
}
__global__ void k_scan3() {
    int i = blockIdx.x * blockDim.x + threadIdx.x;
    if (i >= N_NODES) return;
    int o = g_offs[i] + g_bsum2[i / SCAN_B];
    g_offs[i]   = o;
    g_cursor[i] = o;
}
__global__ void k_fill(const int* __restrict__ ei) {
    int e = blockIdx.x * blockDim.x + threadIdx.x;
    if (e >= N_EDGES) return;
    int r = ei[e];
    int c = ei[N_EDGES + e];
    int pos = atomicAdd(&g_cursor[c], 1);
    float w = (1.0f - ALPHA) * g_dinv[r] * g_dinv[c];
    uint32_t wb = (uint32_t)__half_as_ushort(__float2half_rn(w)) & 0x7FFFu;
    g_csr[pos] = ((uint32_t)r << 15) | wb;
}

// ---------------- GEMM1: h1 = fp16(relu(x @ W1 + b1)), fp16x3 MMA -----------
// Software-pipelined: x tile k+1 prefetched to regs before MMA(k);
// W tiles double-buffered via cp.async (waited one tile late).
#define G1ST   40
#define G1XS   (128 * G1ST)                 // 5120 halves per array
#define G1SMEM ((2 * G1XS + 4 * G1XS) * 2)  // xs_h,xs_l + 2x(ws_h,ws_l) = 61440 B
__global__ void __launch_bounds__(256) k_gemm1(const float* __restrict__ x,
                                               const float* __restrict__ b1) {
    extern __shared__ __half dsm[];
    __half* xs_h = dsm;
    __half* xs_l = dsm + G1XS;
    uint32_t base32 = smem_u32(dsm);

    int tid = threadIdx.x;
    int wid = tid >> 5, lid = tid & 31;
    int g = lid >> 2, tig = lid & 3;
    int wm = wid & 3, wn = wid >> 2;
    int row0 = blockIdx.x * 128;

    float acc[2][8][4];
#pragma unroll
    for (int mt = 0; mt < 2; mt++)
#pragma unroll
        for (int nt = 0; nt < 8; nt++)
#pragma unroll
            for (int i = 0; i < 4; i++) acc[mt][nt][i] = 0.0f;

    // -- pipeline prologue: W(0) async, x(0) to regs --
    float4 xv[4];
    {
        uint32_t wh32 = base32 + (2 * G1XS) * 2;    // buf 0
        uint32_t wl32 = wh32 + G1XS * 2;
#pragma unroll
        for (int i = 0; i < 2; i++) {
            int slot = tid + i * 256;
            int n = slot >> 2, c = slot & 3;
            cp16(wh32 + (n * G1ST + c * 8) * 2, &g_W1h[(size_t)n * F_IN + c * 8]);
            cp16(wl32 + (n * G1ST + c * 8) * 2, &g_W1l[(size_t)n * F_IN + c * 8]);
        }
        asm volatile("cp.async.commit_group;" ::: "memory");
#pragma unroll
        for (int i = 0; i < 4; i++) {
            int slot = tid + i * 256;
            int m = slot >> 3, c4 = slot & 7;
            int grow = row0 + m; if (grow >= N_NODES) grow = N_NODES - 1;
            xv[i] = *(const float4*)&x[(size_t)grow * F_IN + c4 * 4];
        }
    }

    for (int kt = 0; kt < 16; kt++) {
        asm volatile("cp.async.wait_group 0;" ::: "memory");
        // store x(kt) from regs with fp16 hi/lo split
#pragma unroll
        for (int i = 0; i < 4; i++) {
            int slot = tid + i * 256;
            int m = slot >> 3, c4 = slot & 7;
            float4 v = xv[i];
            __half hx0 = __float2half_rn(v.x), hx1 = __float2half_rn(v.y);
            __half hx2 = __float2half_rn(v.z), hx3 = __float2half_rn(v.w);
            __half lx0 = __float2half_rn(v.x - __half2float(hx0));
            __half lx1 = __float2half_rn(v.y - __half2float(hx1));
            __half lx2 = __float2half_rn(v.z - __half2float(hx2));
            __half lx3 = __float2half_rn(v.w - __half2float(hx3));
            __half* ph = &xs_h[m * G1ST + c4 * 4];
            __half* pl = &xs_l[m * G1ST + c4 * 4];
            *(__half2*)ph       = __halves2half2(hx0, hx1);
            *(__half2*)(ph + 2) = __halves2half2(hx2, hx3);
            *(__half2*)pl       = __halves2half2(lx0, lx1);
            *(__half2*)(pl + 2) = __halves2half2(lx2, lx3);
        }
        __syncthreads();

        if (kt < 15) {
            // W(kt+1) async into other buffer
            uint32_t wh32 = base32 + (2 * G1XS + ((kt + 1) & 1) * 2 * G1XS) * 2;
            uint32_t wl32 = wh32 + G1XS * 2;
#pragma unroll
            for (int i = 0; i < 2; i++) {
                int slot = tid + i * 256;
                int n = slot >> 2, c = slot & 3;
                cp16(wh32 + (n * G1ST + c * 8) * 2,
                     &g_W1h[(size_t)n * F_IN + (kt + 1) * 32 + c * 8]);
                cp16(wl32 + (n * G1ST + c * 8) * 2,
                     &g_W1l[(size_t)n * F_IN + (kt + 1) * 32 + c * 8]);
            }
            asm volatile("cp.async.commit_group;" ::: "memory");
            // x(kt+1) to regs — issues before MMAs, overlaps them
#pragma unroll
            for (int i = 0; i < 4; i++) {
                int slot = tid + i * 256;
                int m = slot >> 3, c4 = slot & 7;
                int grow = row0 + m; if (grow >= N_NODES) grow = N_NODES - 1;
                xv[i] = *(const float4*)&x[(size_t)grow * F_IN + (kt + 1) * 32 + c4 * 4];
            }
        }

        __half* ws_h = dsm + 2 * G1XS + (kt & 1) * 2 * G1XS;
        __half* ws_l = ws_h + G1XS;
#pragma unroll
        for (int ks = 0; ks < 2; ks++) {
            int kk = ks * 16;
            uint32_t ah[2][4], al[2][4];
#pragma unroll
            for (int mt = 0; mt < 2; mt++) {
                int m = wm * 32 + mt * 16 + g;
                ah[mt][0] = *(uint32_t*)&xs_h[m * G1ST + kk + 2 * tig];
                ah[mt][1] = *(uint32_t*)&xs_h[(m + 8) * G1ST + kk + 2 * tig];
                ah[mt][2] = *(uint32_t*)&xs_h[m * G1ST + kk + 8 + 2 * tig];
                ah[mt][3] = *(uint32_t*)&xs_h[(m + 8) * G1ST + kk + 8 + 2 * tig];
                al[mt][0] = *(uint32_t*)&xs_l[m * G1ST + kk + 2 * tig];
                al[mt][1] = *(uint32_t*)&xs_l[(m + 8) * G1ST + kk + 2 * tig];
                al[mt][2] = *(uint32_t*)&xs_l[m * G1ST + kk + 8 + 2 * tig];
                al[mt][3] = *(uint32_t*)&xs_l[(m + 8) * G1ST + kk + 8 + 2 * tig];
            }
#pragma unroll
            for (int nt = 0; nt < 8; nt++) {
                int n = wn * 64 + nt * 8 + g;
                uint32_t bh[2], bl[2];
                bh[0] = *(uint32_t*)&ws_h[n * G1ST + kk + 2 * tig];
                bh[1] = *(uint32_t*)&ws_h[n * G1ST + kk + 8 + 2 * tig];
                bl[0] = *(uint32_t*)&ws_l[n * G1ST + kk + 2 * tig];
                bl[1] = *(uint32_t*)&ws_l[n * G1ST + kk + 8 + 2 * tig];
#pragma unroll
                for (int mt = 0; mt < 2; mt++) {
                    mma_f16(acc[mt][nt], ah[mt], bh);
                    mma_f16(acc[mt][nt], ah[mt], bl);
                    mma_f16(acc[mt][nt], al[mt], bh);
                }
            }
        }
        __syncthreads();
    }

#pragma unroll
    for (int nt = 0; nt < 8; nt++) {
        int col = wn * 64 + nt * 8 + tig * 2;
        float2 bb = *(const float2*)&b1[col];
#pragma unroll
        for (int mt = 0; mt < 2; mt++) {
            int r0 = row0 + wm * 32 + mt * 16 + g;
            if (r0 < N_NODES) {
                float ox = acc[mt][nt][0] + bb.x, oy = acc[mt][nt][1] + bb.y;
                ox = ox > 0.f ? ox : 0.f;  oy = oy > 0.f ? oy : 0.f;
                *(__half2*)&g_h1[(size_t)r0 * F_H + col] = __floats2half2_rn(ox, oy);
            }
            if (r0 + 8 < N_NODES) {
                float ox = acc[mt][nt][2] + bb.x, oy = acc[mt][nt][3] + bb.y;
                ox = ox > 0.f ? ox : 0.f;  oy = oy > 0.f ? oy : 0.f;
                *(__half2*)&g_h1[(size_t)(r0 + 8) * F_H + col] = __floats2half2_rn(ox, oy);
            }
        }
    }
}

// ---------------- GEMM2: h0h = fp16(relu(h1 @ W2 + b2)), fp16 MMA -----------
#define G2ST 136
#define G2SMEM ((128 * G2ST + 2 * F_OUT * G2ST) * 2)
__global__ void __launch_bounds__(256) k_gemm2(const float* __restrict__ b2) {
    extern __shared__ __half sm2[];
    __half* hs = sm2;
    __half* wh = sm2 + 128 * G2ST;
    __half* wl = wh + F_OUT * G2ST;
    uint32_t hs32 = smem_u32(hs), wh32 = smem_u32(wh), wl32 = smem_u32(wl);

    int tid = threadIdx.x;
    int wid = tid >> 5, lid = tid & 31;
    int g = lid >> 2, tig = lid & 3;
    int row0 = blockIdx.x * 128;

#pragma unroll
    for (int i = 0; i < 8; i++) {
        int slot = tid + i * 256;
        int m = slot >> 4, c = slot & 15;
        int grow = row0 + m; if (grow >= N_NODES) grow = N_NODES - 1;
        cp16(hs32 + (m * G2ST + c * 8) * 2, &g_h1[(size_t)grow * F_H + c * 8]);
    }
#pragma unroll
    for (int i = 0; i < 3; i++) {
        int slot = tid + i * 256;
        if (slot < F_OUT * 16) {
            int n = slot >> 4, c = slot & 15;
            cp16(wh32 + (n * G2ST + c * 8) * 2, &g_W2Th[(size_t)n * F_H + c * 8]);
            cp16(wl32 + (n * G2ST + c * 8) * 2, &g_W2Tl[(size_t)n * F_H + c * 8]);
        }
    }
    asm volatile("cp.async.commit_group;" ::: "memory");
    asm volatile("cp.async.wait_group 0;" ::: "memory");
    __syncthreads();

    float acc[5][4];
#pragma unroll
    for (int nt = 0; nt < 5; nt++)
#pragma unroll
        for (int i = 0; i < 4; i++) acc[nt][i] = 0.0f;

#pragma unroll
    for (int ks = 0; ks < 8; ks++) {
        int kk = ks * 16;
        int m = wid * 16 + g;
        uint32_t a[4];
        a[0] = *(uint32_t*)&hs[m * G2ST + kk + 2 * tig];
        a[1] = *(uint32_t*)&hs[(m + 8) * G2ST + kk + 2 * tig];
        a[2] = *(uint32_t*)&hs[m * G2ST + kk + 8 + 2 * tig];
        a[3] = *(uint32_t*)&hs[(m + 8) * G2ST + kk + 8 + 2 * tig];
#pragma unroll
        for (int nt = 0; nt < 5; nt++) {
            int n = nt * 8 + g;
            uint32_t bhv[2], blv[2];
            bhv[0] = *(uint32_t*)&wh[n * G2ST + kk + 2 * tig];
            bhv[1] = *(uint32_t*)&wh[n * G2ST + kk + 8 + 2 * tig];
            blv[0] = *(uint32_t*)&wl[n * G2ST + kk + 2 * tig];
            blv[1] = *(uint32_t*)&wl[n * G2ST + kk + 8 + 2 * tig];
            mma_f16(acc[nt], a, bhv);
            mma_f16(acc[nt], a, blv);
        }
    }

#pragma unroll
    for (int nt = 0; nt < 5; nt++) {
        int col = nt * 8 + tig * 2;
        float2 bb = *(const float2*)&b2[col];
        int r0 = row0 + wid * 16 + g;
        if (r0 < N_NODES) {
            float ox = acc[nt][0] + bb.x, oy = acc[nt][1] + bb.y;
            ox = ox > 0.f ? ox : 0.f;  oy = oy > 0.f ? oy : 0.f;
            *(__half2*)&g_h0h[(size_t)r0 * F_PAD + col] = __floats2half2_rn(ox, oy);
        }
        if (r0 + 8 < N_NODES) {
            float ox = acc[nt][2] + bb.x, oy = acc[nt][3] + bb.y;
            ox = ox > 0.f ? ox : 0.f;  oy = oy > 0.f ? oy : 0.f;
            *(__half2*)&g_h0h[(size_t)(r0 + 8) * F_PAD + col] = __floats2half2_rn(ox, oy);
        }
    }
}

// ---------------- propagation: warp-per-node pull, SW-pipelined CSR ---------
// 6 groups x 5 lanes; group handles edges e0+group+6k. Depth-3 pipeline:
// CSR for batch k+1 issued before FMAs of batch k; guarded addresses,
// weight-zeroed tail lanes (no divergence inside a group).
#define NPW 8
template <bool LAST>
__global__ void __launch_bounds__(256) k_pull_w(const __half* __restrict__ srcp,
                                                void* __restrict__ dstv) {
    int lane = threadIdx.x & 31;
    int gw   = blockIdx.x * 8 + (threadIdx.x >> 5);
    int n0 = gw * NPW;
    if (n0 >= N_NODES) return;
    int n1 = n0 + NPW; if (n1 > N_NODES) n1 = N_NODES;

    const char* sbase = (const char*)srcp;
    const uint4* s4   = (const uint4*)srcp;
    const uint4* h4   = (const uint4*)g_h0h;
    int group = lane / 5;
    int q     = lane % 5;
    int qb    = q * 16;
    bool act  = lane < 30;

    for (int n = n0; n < n1; n++) {
        int e0 = g_offs[n], e1 = g_offs[n + 1];
        float2 acc[4];
#pragma unroll
        for (int j = 0; j < 4; j++) acc[j] = make_float2(0.f, 0.f);

        if (act) {
            int e = e0 + group;
            bool v0 = e < e1, v1 = e + 6 < e1, v2 = e + 12 < e1;
            uint32_t p0 = __ldg(&g_csr[v0 ? e      : e0]);
            uint32_t p1 = __ldg(&g_csr[v1 ? e + 6  : e0]);
            uint32_t p2 = __ldg(&g_csr[v2 ? e + 12 : e0]);
            while (v0) {
                uint4 r0 = __ldg((const uint4*)(sbase + ((p0 >> 8) & 0xFFFFFF80u) + qb));
                uint4 r1 = __ldg((const uint4*)(sbase + (((v1 ? p1 : p0) >> 8) & 0xFFFFFF80u) + qb));
                uint4 r2 = __ldg((const uint4*)(sbase + (((v2 ? p2 : p0) >> 8) & 0xFFFFFF80u) + qb));
                int en = e + 18;
                bool w0v = en < e1, w1v = en + 6 < e1, w2v = en + 12 < e1;
                uint32_t q0 = __ldg(&g_csr[w0v ? en      : e0]);
                uint32_t q1 = __ldg(&g_csr[w1v ? en + 6  : e0]);
                uint32_t q2 = __ldg(&g_csr[w2v ? en + 12 : e0]);
                float f0 = dec_w(p0);
                float f1 = v1 ? dec_w(p1) : 0.f;
                float f2 = v2 ? dec_w(p2) : 0.f;
                const __half2* a0 = (const __half2*)&r0;
                const __half2* a1 = (const __half2*)&r1;
                const __half2* a2 = (const __half2*)&r2;
#pragma unroll
                for (int j = 0; j < 4; j++) {
                    float2 x0 = __half22float2(a0[j]);
                    float2 x1 = __half22float2(a1[j]);
                    float2 x2 = __half22float2(a2[j]);
                    acc[j].x = fmaf(f0, x0.x, acc[j].x); acc[j].y = fmaf(f0, x0.y, acc[j].y);
                    acc[j].x = fmaf(f1, x1.x, acc[j].x); acc[j].y = fmaf(f1, x1.y, acc[j].y);
                    acc[j].x = fmaf(f2, x2.x, acc[j].x); acc[j].y = fmaf(f2, x2.y, acc[j].y);
                }
                p0 = q0; p1 = q1; p2 = q2;
                v0 = w0v; v1 = w1v; v2 = w2v;
                e = en;
            }
        }

        // reduce 6 groups: round1 (+15), then snapshot (+5, +10)
#pragma unroll
        for (int j = 0; j < 4; j++) {
            acc[j].x += __shfl_sync(0xFFFFFFFFu, acc[j].x, (lane + 15) & 31);
            acc[j].y += __shfl_sync(0xFFFFFFFFu, acc[j].y, (lane + 15) & 31);
        }
#pragma unroll
        for (int j = 0; j < 4; j++) {
            float tx1 = __shfl_sync(0xFFFFFFFFu, acc[j].x, (lane + 5) & 31);
            float ty1 = __shfl_sync(0xFFFFFFFFu, acc[j].y, (lane + 5) & 31);
            float tx2 = __shfl_sync(0xFFFFFFFFu, acc[j].x, (lane + 10) & 31);
            float ty2 = __shfl_sync(0xFFFFFFFFu, acc[j].y, (lane + 10) & 31);
            acc[j].x += tx1 + tx2;
            acc[j].y += ty1 + ty2;
        }

        if (lane < 5) {
            float sc = g_selfc[n];
            uint4 hraw = h4[n * 8 + lane];
            uint4 sraw = s4[n * 8 + lane];
            const __half2* hh = (const __half2*)&hraw;
            const __half2* sh = (const __half2*)&sraw;
#pragma unroll
            for (int j = 0; j < 4; j++) {
                float2 hv = __half22float2(hh[j]);
                float2 sv = __half22float2(sh[j]);
                acc[j].x += fmaf(sc, sv.x, ALPHA * hv.x);
                acc[j].y += fmaf(sc, sv.y, ALPHA * hv.y);
            }
            if (LAST) {
                float* out = (float*)dstv;
                float4 o0 = make_float4(acc[0].x, acc[0].y, acc[1].x, acc[1].y);
                float4 o1 = make_float4(acc[2].x, acc[2].y, acc[3].x, acc[3].y);
                *(float4*)&out[(size_t)n * F_OUT + lane * 8]     = o0;
                *(float4*)&out[(size_t)n * F_OUT + lane * 8 + 4] = o1;
            } else {
                uint4 o;
                __half2* oh = (__half2*)&o;
#pragma unroll
                for (int j = 0; j < 4; j++) oh[j] = __float22half2_rn(acc[j]);
                ((uint4*)dstv)[n * 8 + lane] = o;
            }
        }
    }
}

// ---------------- launcher ---------------------------------------------------
extern "C" void kernel_launch(void* const* d_in, const int* in_sizes, int n_in,
                              void* d_out, int out_size) {
    const float* x  = (const float*)d_in[0];
    const int*   ei = (const int*)  d_in[1];
    const float* W1 = (const float*)d_in[2];
    const float* b1 = (const float*)d_in[3];
    const float* W2 = (const float*)d_in[4];
    const float* b2 = (const float*)d_in[5];

    __half *zA, *zB, *h0h;
    cudaGetSymbolAddress((void**)&zA,  g_zhA);
    cudaGetSymbolAddress((void**)&zB,  g_zhB);
    cudaGetSymbolAddress((void**)&h0h, g_h0h);

    cudaFuncSetAttribute(k_gemm1, cudaFuncAttributeMaxDynamicSharedMemorySize, G1SMEM);
    cudaFuncSetAttribute(k_gemm2, cudaFuncAttributeMaxDynamicSharedMemorySize, G2SMEM);

    // CSR build + weight prep
    k_prep0<<<(N_NODES + 255) / 256, 256>>>(W1, W2);
    k_count<<<(N_EDGES + 255) / 256, 256>>>(ei);
    k_scan1<<<NBLK, SCAN_B>>>();
    k_scan2<<<1, 256>>>();
    k_scan3<<<(N_NODES + 255) / 256, 256>>>();
    k_fill <<<(N_EDGES + 255) / 256, 256>>>(ei);

    // MLP encoder (fp16 tensor-core MMA, pipelined)
    k_gemm1<<<(N_NODES + 127) / 128, 256, G1SMEM>>>(x, b1);
    k_gemm2<<<(N_NODES + 127) / 128, 256, G2SMEM>>>(b2);

    // APPNP propagation (warp-per-node pull, fp16 z, packed CSR, pipelined)
    int nwarps = (N_NODES + NPW - 1) / NPW;
    int pgrid  = (nwarps + 7) / 8;
    const __half* src = h0h;
    for (int it = 0; it < K_ITERS - 1; it++) {
        __half* dst = (it & 1) ? zB : zA;
        k_pull_w<false><<<pgrid, 256>>>(src, dst);
        src = dst;
    }
    k_pull_w<true><<<pgrid, 256>>>(src, d_out);
}

// round 14
// speedup vs baseline: 1.0031x; 1.0031x over previous
#include <cuda_runtime.h>
#include <cuda_fp16.h>
#include <cstdint>

#define N_NODES 100000
#define N_EDGES 3200000
#define F_IN    512
#define F_H     128
#define F_OUT   40
#define F_PAD   64          // padded row length in halves (128 B rows)
#define K_ITERS 20
#define ALPHA   0.1f

#define SCAN_B  512
#define NBLK    ((N_NODES + SCAN_B - 1) / SCAN_B)   // 196

// ---------------- scratch (device globals; no runtime allocation) ----------
__device__ __half   g_h1[(size_t)N_NODES * F_H];
__device__ __half   g_W1h[(size_t)F_H * F_IN];
__device__ __half   g_W1l[(size_t)F_H * F_IN];
__device__ __half   g_W2Th[(size_t)F_OUT * F_H];
__device__ __half   g_W2Tl[(size_t)F_OUT * F_H];
__device__ __half   g_h0h[(size_t)N_NODES * F_PAD];   // padded 128B rows
__device__ __half   g_zhA[(size_t)N_NODES * F_PAD];
__device__ __half   g_zhB[(size_t)N_NODES * F_PAD];
__device__ int      g_cnt[N_NODES];
__device__ int      g_offs[N_NODES + 1];
__device__ int      g_cursor[N_NODES];
__device__ int      g_bsum[NBLK];
__device__ int      g_bsum2[NBLK];
__device__ float    g_dinv[N_NODES];
__device__ float    g_selfc[N_NODES];
__device__ uint32_t g_csr[N_EDGES];     // idx(17b)<<15 | half_bits(w)&0x7FFF

// ---------------- helpers ----------------------------------------------------
__device__ __forceinline__ void cp16(uint32_t s, const void* g) {
    asm volatile("cp.async.cg.shared.global [%0], [%1], 16;" :: "r"(s), "l"(g));
}
__device__ __forceinline__ uint32_t smem_u32(const void* p) {
    uint32_t a;
    asm("{ .reg .u64 t; cvta.to.shared.u64 t, %1; cvt.u32.u64 %0, t; }" : "=r"(a) : "l"(p));
    return a;
}
__device__ __forceinline__ void mma_f16(float* c, const uint32_t* a, const uint32_t* b) {
    asm volatile(
        "mma.sync.aligned.m16n8k16.row.col.f32.f16.f16.f32 "
        "{%0,%1,%2,%3}, {%4,%5,%6,%7}, {%8,%9}, {%0,%1,%2,%3};"
        : "+f"(c[0]), "+f"(c[1]), "+f"(c[2]), "+f"(c[3])
        : "r"(a[0]), "r"(a[1]), "r"(a[2]), "r"(a[3]), "r"(b[0]), "r"(b[1]));
}

// ---------------- prep kernels ----------------------------------------------
__global__ void k_prep0(const float* __restrict__ W1, const float* __restrict__ W2) {
    int i = blockIdx.x * blockDim.x + threadIdx.x;
    if (i < F_IN * F_H) {
        int k = i >> 7, n = i & 127;
        float v = W1[i];
        __half h = __float2half_rn(v);
        g_W1h[(size_t)n * F_IN + k] = h;
        g_W1l[(size_t)n * F_IN + k] = __float2half_rn(v - __half2float(h));
    }
    if (i < F_H * F_OUT) {
        int k = i / F_OUT, n = i % F_OUT;
        float v = W2[i];
        __half h = __float2half_rn(v);
        g_W2Th[(size_t)n * F_H + k] = h;
        g_W2Tl[(size_t)n * F_H + k] = __float2half_rn(v - __half2float(h));
    }
    if (i < N_NODES) g_cnt[i] = 0;
}
__global__ void k_count(const int* __restrict__ ei) {
    int e = blockIdx.x * blockDim.x + threadIdx.x;
    if (e < N_EDGES) atomicAdd(&g_cnt[ei[N_EDGES + e]], 1);
}
__global__ void k_scan1() {
    __shared__ int s[SCAN_B];
    int i = blockIdx.x * SCAN_B + threadIdx.x;
    int v = (i < N_NODES) ? g_cnt[i] : 0;
    if (i < N_NODES) {
        float d = (float)(v + 1);
        float r = rsqrtf(d);
        g_dinv[i]  = r;
        g_selfc[i] = (1.0f - ALPHA) * r * r;
    }
    s[threadIdx.x] = v;
    __syncthreads();
#pragma unroll
    for (int off = 1; off < SCAN_B; off <<= 1) {
        int t = (threadIdx.x >= off) ? s[threadIdx.x - off] : 0;
        __syncthreads();
        s[threadIdx.x] += t;
        __syncthreads();
    }
    if (i < N_NODES) g_offs[i] = s[threadIdx.x] - v;
    if (threadIdx.x == SCAN_B - 1) g_bsum[blockIdx.x] = s[SCAN_B - 1];
}
__global__ void k_scan2() {
    __shared__ int s[256];
    int t = threadIdx.x;
    int v = (t < NBLK) ? g_bsum[t] : 0;
    s[t] = v;
    __syncthreads();
#pragma unroll
    for (int off = 1; off < 256; off <<= 1) {
        int u = (t >= off) ? s[t - off] : 0;
        __syncthreads();
        s[t] += u;
        __syncthreads();
    }
    if (t < NBLK) g_bsum2[t] = s[t] - v;
    if (t == 0) g_offs[N_NODES] = s[255];
}
__global__ void k_scan3() {
    int i = blockIdx.x * blockDim.x + threadIdx.x;
    if (i >= N_NODES) return;
    int o = g_offs[i] + g_bsum2[i / SCAN_B];
    g_offs[i]   = o;
    g_cursor[i] = o;
}
__global__ void k_fill(const int* __restrict__ ei) {
    int e = blockIdx.x * blockDim.x + threadIdx.x;
    if (e >= N_EDGES) return;
    int r = ei[e];
    int c = ei[N_EDGES + e];
    int pos = atomicAdd(&g_cursor[c], 1);
    float w = (1.0f - ALPHA) * g_dinv[r] * g_dinv[c];
    uint32_t wb = (uint32_t)__half_as_ushort(__float2half_rn(w)) & 0x7FFFu;
    g_csr[pos] = ((uint32_t)r << 15) | wb;
}

// ---------------- GEMM1: h1 = fp16(relu(x @ W1 + b1)), fp16x3 MMA -----------
#define G1ST 40
__global__ void __launch_bounds__(256) k_gemm1(const float* __restrict__ x,
                                               const float* __restrict__ b1) {
    __shared__ __half xs_h[128 * G1ST], xs_l[128 * G1ST];
    __shared__ __half ws_h[128 * G1ST], ws_l[128 * G1ST];
    uint32_t wsh32 = smem_u32(ws_h), wsl32 = smem_u32(ws_l);

    int tid = threadIdx.x;
    int wid = tid >> 5, lid = tid & 31;
    int g = lid >> 2, tig = lid & 3;
    int wm = wid & 3, wn = wid >> 2;
    int row0 = blockIdx.x * 128;

    float acc[2][8][4];
#pragma unroll
    for (int mt = 0; mt < 2; mt++)
#pragma unroll
        for (int nt = 0; nt < 8; nt++)
#pragma unroll
            for (int i = 0; i < 4; i++) acc[mt][nt][i] = 0.0f;

    for (int kt = 0; kt < 16; kt++) {
#pragma unroll
        for (int i = 0; i < 2; i++) {
            int slot = tid + i * 256;
            int n = slot >> 2, c = slot & 3;
            cp16(wsh32 + (n * G1ST + c * 8) * 2, &g_W1h[(size_t)n * F_IN + kt * 32 + c * 8]);
            cp16(wsl32 + (n * G1ST + c * 8) * 2, &g_W1l[(size_t)n * F_IN + kt * 32 + c * 8]);
        }
        asm volatile("cp.async.commit_group;" ::: "memory");
#pragma unroll
        for (int i = 0; i < 4; i++) {
            int slot = tid + i * 256;
            int m = slot >> 3, c4 = slot & 7;
            int grow = row0 + m; if (grow >= N_NODES) grow = N_NODES - 1;
            float4 v = *(const float4*)&x[(size_t)grow * F_IN + kt * 32 + c4 * 4];
            __half hx0 = __float2half_rn(v.x), hx1 = __float2half_rn(v.y);
            __half hx2 = __float2half_rn(v.z), hx3 = __float2half_rn(v.w);
            __half lx0 = __float2half_rn(v.x - __half2float(hx0));
            __half lx1 = __float2half_rn(v.y - __half2float(hx1));
            __half lx2 = __float2half_rn(v.z - __half2float(hx2));
            __half lx3 = __float2half_rn(v.w - __half2float(hx3));
            __half* ph = &xs_h[m * G1ST + c4 * 4];
            __half* pl = &xs_l[m * G1ST + c4 * 4];
            *(__half2*)ph       = __halves2half2(hx0, hx1);
            *(__half2*)(ph + 2) = __halves2half2(hx2, hx3);
            *(__half2*)pl       = __halves2half2(lx0, lx1);
            *(__half2*)(pl + 2) = __halves2half2(lx2, lx3);
        }
        asm volatile("cp.async.wait_group 0;" ::: "memory");
        __syncthreads();

#pragma unroll
        for (int ks = 0; ks < 2; ks++) {
            int kk = ks * 16;
            uint32_t ah[2][4], al[2][4];
#pragma unroll
            for (int mt = 0; mt < 2; mt++) {
                int m = wm * 32 + mt * 16 + g;
                ah[mt][0] = *(uint32_t*)&xs_h[m * G1ST + kk + 2 * tig];
                ah[mt][1] = *(uint32_t*)&xs_h[(m + 8) * G1ST + kk + 2 * tig];
                ah[mt][2] = *(uint32_t*)&xs_h[m * G1ST + kk + 8 + 2 * tig];
                ah[mt][3] = *(uint32_t*)&xs_h[(m + 8) * G1ST + kk + 8 + 2 * tig];
                al[mt][0] = *(uint32_t*)&xs_l[m * G1ST + kk + 2 * tig];
                al[mt][1] = *(uint32_t*)&xs_l[(m + 8) * G1ST + kk + 2 * tig];
                al[mt][2] = *(uint32_t*)&xs_l[m * G1ST + kk + 8 + 2 * tig];
                al[mt][3] = *(uint32_t*)&xs_l[(m + 8) * G1ST + kk + 8 + 2 * tig];
            }
#pragma unroll
            for (int nt = 0; nt < 8; nt++) {
                int n = wn * 64 + nt * 8 + g;
                uint32_t bh[2], bl[2];
                bh[0] = *(uint32_t*)&ws_h[n * G1ST + kk + 2 * tig];
                bh[1] = *(uint32_t*)&ws_h[n * G1ST + kk + 8 + 2 * tig];
                bl[0] = *(uint32_t*)&ws_l[n * G1ST + kk + 2 * tig];
                bl[1] = *(uint32_t*)&ws_l[n * G1ST + kk + 8 + 2 * tig];
#pragma unroll
                for (int mt = 0; mt < 2; mt++) {
                    mma_f16(acc[mt][nt], ah[mt], bh);
                    mma_f16(acc[mt][nt], ah[mt], bl);
                    mma_f16(acc[mt][nt], al[mt], bh);
                }
            }
        }
        __syncthreads();
    }

#pragma unroll
    for (int nt = 0; nt < 8; nt++) {
        int col = wn * 64 + nt * 8 + tig * 2;
        float2 bb = *(const float2*)&b1[col];
#pragma unroll
        for (int mt = 0; mt < 2; mt++) {
            int r0 = row0 + wm * 32 + mt * 16 + g;
            if (r0 < N_NODES) {
                float ox = acc[mt][nt][0] + bb.x, oy = acc[mt][nt][1] + bb.y;
                ox = ox > 0.f ? ox : 0.f;  oy = oy > 0.f ? oy : 0.f;
                *(__half2*)&g_h1[(size_t)r0 * F_H + col] = __floats2half2_rn(ox, oy);
            }
            if (r0 + 8 < N_NODES) {
                float ox = acc[mt][nt][2] + bb.x, oy = acc[mt][nt][3] + bb.y;
                ox = ox > 0.f ? ox : 0.f;  oy = oy > 0.f ? oy : 0.f;
                *(__half2*)&g_h1[(size_t)(r0 + 8) * F_H + col] = __floats2half2_rn(ox, oy);
            }
        }
    }
}

// ---------------- GEMM2: h0h = fp16(relu(h1 @ W2 + b2)), fp16 MMA -----------
#define G2ST 136
#define G2SMEM ((128 * G2ST + 2 * F_OUT * G2ST) * 2)
__global__ void __launch_bounds__(256) k_gemm2(const float* __restrict__ b2) {
    extern __shared__ __half sm2[];
    __half* hs = sm2;
    __half* wh = sm2 + 128 * G2ST;
    __half* wl = wh + F_OUT * G2ST;
    uint32_t hs32 = smem_u32(hs), wh32 = smem_u32(wh), wl32 = smem_u32(wl);

    int tid = threadIdx.x;
    int wid = tid >> 5, lid = tid & 31;
    int g = lid >> 2, tig = lid & 3;
    int row0 = blockIdx.x * 128;

#pragma unroll
    for (int i = 0; i < 8; i++) {
        int slot = tid + i * 256;
        int m = slot >> 4, c = slot & 15;
        int grow = row0 + m; if (grow >= N_NODES) grow = N_NODES - 1;
        cp16(hs32 + (m * G2ST + c * 8) * 2, &g_h1[(size_t)grow * F_H + c * 8]);
    }
#pragma unroll
    for (int i = 0; i < 3; i++) {
        int slot = tid + i * 256;
        if (slot < F_OUT * 16) {
            int n = slot >> 4, c = slot & 15;
            cp16(wh32 + (n * G2ST + c * 8) * 2, &g_W2Th[(size_t)n * F_H + c * 8]);
            cp16(wl32 + (n * G2ST + c * 8) * 2, &g_W2Tl[(size_t)n * F_H + c * 8]);
        }
    }
    asm volatile("cp.async.commit_group;" ::: "memory");
    asm volatile("cp.async.wait_group 0;" ::: "memory");
    __syncthreads();

    float acc[5][4];
#pragma unroll
    for (int nt = 0; nt < 5; nt++)
#pragma unroll
        for (int i = 0; i < 4; i++) acc[nt][i] = 0.0f;

#pragma unroll
    for (int ks = 0; ks < 8; ks++) {
        int kk = ks * 16;
        int m = wid * 16 + g;
        uint32_t a[4];
        a[0] = *(uint32_t*)&hs[m * G2ST + kk + 2 * tig];
        a[1] = *(uint32_t*)&hs[(m + 8) * G2ST + kk + 2 * tig];
        a[2] = *(uint32_t*)&hs[m * G2ST + kk + 8 + 2 * tig];
        a[3] = *(uint32_t*)&hs[(m + 8) * G2ST + kk + 8 + 2 * tig];
#pragma unroll
        for (int nt = 0; nt < 5; nt++) {
            int n = nt * 8 + g;
            uint32_t bhv[2], blv[2];
            bhv[0] = *(uint32_t*)&wh[n * G2ST + kk + 2 * tig];
            bhv[1] = *(uint32_t*)&wh[n * G2ST + kk + 8 + 2 * tig];
            blv[0] = *(uint32_t*)&wl[n * G2ST + kk + 2 * tig];
            blv[1] = *(uint32_t*)&wl[n * G2ST + kk + 8 + 2 * tig];
            mma_f16(acc[nt], a, bhv);
            mma_f16(acc[nt], a, blv);
        }
    }

#pragma unroll
    for (int nt = 0; nt < 5; nt++) {
        int col = nt * 8 + tig * 2;
        float2 bb = *(const float2*)&b2[col];
        int r0 = row0 + wid * 16 + g;
        if (r0 < N_NODES) {
            float ox = acc[nt][0] + bb.x, oy = acc[nt][1] + bb.y;
            ox = ox > 0.f ? ox : 0.f;  oy = oy > 0.f ? oy : 0.f;
            *(__half2*)&g_h0h[(size_t)r0 * F_PAD + col] = __floats2half2_rn(ox, oy);
        }
        if (r0 + 8 < N_NODES) {
            float ox = acc[nt][2] + bb.x, oy = acc[nt][3] + bb.y;
            ox = ox > 0.f ? ox : 0.f;  oy = oy > 0.f ? oy : 0.f;
            *(__half2*)&g_h0h[(size_t)(r0 + 8) * F_PAD + col] = __floats2half2_rn(ox, oy);
        }
    }
}

// ---------------- propagation: grid-stride warp-per-node pull ---------------
// Fixed grid (1184 CTAs x 8 warps = 9472 warps); each warp strides over nodes
// n = gw, gw+9472, ... (10-11 nodes/warp) -> integer wave count, ±4% imbalance.
// Per node: 6 groups x 5 lanes split the edge list (R9 body, unroll 4).
#define PGRID   1184
#define TOTWARP (PGRID * 8)
template <bool LAST>
__global__ void __launch_bounds__(256) k_pull_w(const __half* __restrict__ srcp,
                                                void* __restrict__ dstv) {
    int lane = threadIdx.x & 31;
    int gw   = blockIdx.x * 8 + (threadIdx.x >> 5);

    const char* sbase = (const char*)srcp;
    const uint4* s4   = (const uint4*)srcp;
    const uint4* h4   = (const uint4*)g_h0h;
    int group = lane / 5;
    int q     = lane % 5;
    int qb    = q * 16;
    bool act  = lane < 30;

    for (int n = gw; n < N_NODES; n += TOTWARP) {
        int e0 = g_offs[n], e1 = g_offs[n + 1];
        float2 acc[4];
#pragma unroll
        for (int j = 0; j < 4; j++) acc[j] = make_float2(0.f, 0.f);

        if (act) {
            int e = e0 + group;
            for (; e + 18 < e1; e += 24) {
                uint32_t p0 = __ldg(&g_csr[e]);
                uint32_t p1 = __ldg(&g_csr[e + 6]);
                uint32_t p2 = __ldg(&g_csr[e + 12]);
                uint32_t p3 = __ldg(&g_csr[e + 18]);
                uint4 r0 = __ldg((const uint4*)(sbase + ((p0 >> 8) & 0xFFFFFF80u) + qb));
                uint4 r1 = __ldg((const uint4*)(sbase + ((p1 >> 8) & 0xFFFFFF80u) + qb));
                uint4 r2 = __ldg((const uint4*)(sbase + ((p2 >> 8) & 0xFFFFFF80u) + qb));
                uint4 r3 = __ldg((const uint4*)(sbase + ((p3 >> 8) & 0xFFFFFF80u) + qb));
                float w0 = __half2float(__ushort_as_half((unsigned short)(p0 & 0x7FFFu)));
                float w1 = __half2float(__ushort_as_half((unsigned short)(p1 & 0x7FFFu)));
                float w2 = __half2float(__ushort_as_half((unsigned short)(p2 & 0x7FFFu)));
                float w3 = __half2float(__ushort_as_half((unsigned short)(p3 & 0x7FFFu)));
                const __half2* a0 = (const __half2*)&r0;
                const __half2* a1 = (const __half2*)&r1;
                const __half2* a2 = (const __half2*)&r2;
                const __half2* a3 = (const __half2*)&r3;
#pragma unroll
                for (int j = 0; j < 4; j++) {
                    float2 v0 = __half22float2(a0[j]);
                    float2 v1 = __half22float2(a1[j]);
                    float2 v2 = __half22float2(a2[j]);
                    float2 v3 = __half22float2(a3[j]);
                    acc[j].x = fmaf(w0, v0.x, acc[j].x); acc[j].y = fmaf(w0, v0.y, acc[j].y);
                    acc[j].x = fmaf(w1, v1.x, acc[j].x); acc[j].y = fmaf(w1, v1.y, acc[j].y);
                    acc[j].x = fmaf(w2, v2.x, acc[j].x); acc[j].y = fmaf(w2, v2.y, acc[j].y);
                    acc[j].x = fmaf(w3, v3.x, acc[j].x); acc[j].y = fmaf(w3, v3.y, acc[j].y);
                }
            }
            for (; e < e1; e += 6) {
                uint32_t p = __ldg(&g_csr[e]);
                uint4 r = __ldg((const uint4*)(sbase + ((p >> 8) & 0xFFFFFF80u) + qb));
                float w = __half2float(__ushort_as_half((unsigned short)(p & 0x7FFFu)));
                const __half2* a = (const __half2*)&r;
#pragma unroll
                for (int j = 0; j < 4; j++) {
                    float2 v = __half22float2(a[j]);
                    acc[j].x = fmaf(w, v.x, acc[j].x);
                    acc[j].y = fmaf(w, v.y, acc[j].y);
                }
            }
        }

        // reduce 6 groups: round1 (+15), then snapshot (+5, +10)
#pragma unroll
        for (int j = 0; j < 4; j++) {
            acc[j].x += __shfl_sync(0xFFFFFFFFu, acc[j].x, (lane + 15) & 31);
            acc[j].y += __shfl_sync(0xFFFFFFFFu, acc[j].y, (lane + 15) & 31);
        }
#pragma unroll
        for (int j = 0; j < 4; j++) {
            float tx1 = __shfl_sync(0xFFFFFFFFu, acc[j].x, (lane + 5) & 31);
            float ty1 = __shfl_sync(0xFFFFFFFFu, acc[j].y, (lane + 5) & 31);
            float tx2 = __shfl_sync(0xFFFFFFFFu, acc[j].x, (lane + 10) & 31);
            float ty2 = __shfl_sync(0xFFFFFFFFu, acc[j].y, (lane + 10) & 31);
            acc[j].x += tx1 + tx2;
            acc[j].y += ty1 + ty2;
        }

        if (lane < 5) {
            float sc = g_selfc[n];
            uint4 hraw = h4[n * 8 + lane];
            uint4 sraw = s4[n * 8 + lane];
            const __half2* hh = (const __half2*)&hraw;
            const __half2* sh = (const __half2*)&sraw;
#pragma unroll
            for (int j = 0; j < 4; j++) {
                float2 hv = __half22float2(hh[j]);
                float2 sv = __half22float2(sh[j]);
                acc[j].x += fmaf(sc, sv.x, ALPHA * hv.x);
                acc[j].y += fmaf(sc, sv.y, ALPHA * hv.y);
            }
            if (LAST) {
                float* out = (float*)dstv;
                float4 o0 = make_float4(acc[0].x, acc[0].y, acc[1].x, acc[1].y);
                float4 o1 = make_float4(acc[2].x, acc[2].y, acc[3].x, acc[3].y);
                *(float4*)&out[(size_t)n * F_OUT + lane * 8]     = o0;
                *(float4*)&out[(size_t)n * F_OUT + lane * 8 + 4] = o1;
            } else {
                uint4 o;
                __half2* oh = (__half2*)&o;
#pragma unroll
                for (int j = 0; j < 4; j++) oh[j] = __float22half2_rn(acc[j]);
                ((uint4*)dstv)[n * 8 + lane] = o;
            }
        }
    }
}

// ---------------- launcher ---------------------------------------------------
extern "C" void kernel_launch(void* const* d_in, const int* in_sizes, int n_in,
                              void* d_out, int out_size) {
    const float* x  = (const float*)d_in[0];
    const int*   ei = (const int*)  d_in[1];
    const float* W1 = (const float*)d_in[2];
    const float* b1 = (const float*)d_in[3];
    const float* W2 = (const float*)d_in[4];
    const float* b2 = (const float*)d_in[5];

    __half *zA, *zB, *h0h;
    cudaGetSymbolAddress((void**)&zA,  g_zhA);
    cudaGetSymbolAddress((void**)&zB,  g_zhB);
    cudaGetSymbolAddress((void**)&h0h, g_h0h);

    cudaFuncSetAttribute(k_gemm2, cudaFuncAttributeMaxDynamicSharedMemorySize, G2SMEM);

    // CSR build + weight prep
    k_prep0<<<(N_NODES + 255) / 256, 256>>>(W1, W2);
    k_count<<<(N_EDGES + 255) / 256, 256>>>(ei);
    k_scan1<<<NBLK, SCAN_B>>>();
    k_scan2<<<1, 256>>>();
    k_scan3<<<(N_NODES + 255) / 256, 256>>>();
    k_fill <<<(N_EDGES + 255) / 256, 256>>>(ei);

    // MLP encoder (fp16 tensor-core MMA)
    k_gemm1<<<(N_NODES + 127) / 128, 256>>>(x, b1);
    k_gemm2<<<(N_NODES + 127) / 128, 256, G2SMEM>>>(b2);

    // APPNP propagation (grid-stride warp-per-node pull, fp16 z, packed CSR)
    const __half* src = h0h;
    for (int it = 0; it < K_ITERS - 1; it++) {
        __half* dst = (it & 1) ? zB : zA;
        k_pull_w<false><<<PGRID, 256>>>(src, dst);
        src = dst;
    }
    k_pull_w<true><<<PGRID, 256>>>(src, d_out);
}

// round 16
// speedup vs baseline: 1.0718x; 1.0685x over previous
#include <cuda_runtime.h>
#include <cuda_fp16.h>
#include <cstdint>

#define N_NODES 100000
#define N_EDGES 3200000
#define F_IN    512
#define F_H     128
#define F_OUT   40
#define F_PAD   64          // padded row length in halves (128 B rows)
#define K_ITERS 20
#define ALPHA   0.1f

#define SCAN_B  512
#define NBLK    ((N_NODES + SCAN_B - 1) / SCAN_B)   // 196

// ---------------- scratch (device globals; no runtime allocation) ----------
__device__ __half   g_h1[(size_t)N_NODES * F_H];
__device__ __half   g_W1h[(size_t)F_H * F_IN];
__device__ __half   g_W1l[(size_t)F_H * F_IN];
__device__ __half   g_W2Th[(size_t)F_OUT * F_H];
__device__ __half   g_W2Tl[(size_t)F_OUT * F_H];
__device__ __half   g_h0h[(size_t)N_NODES * F_PAD];   // padded 128B rows
__device__ __half   g_zhA[(size_t)N_NODES * F_PAD];
__device__ __half   g_zhB[(size_t)N_NODES * F_PAD];
__device__ int      g_cnt[N_NODES];
__device__ int      g_offs[N_NODES + 1];
__device__ int      g_cursor[N_NODES];
__device__ int      g_bsum[NBLK];
__device__ int      g_bsum2[NBLK];
__device__ float    g_dinv[N_NODES];
__device__ float    g_selfc[N_NODES];
__device__ uint32_t g_csr[N_EDGES];     // idx(17b)<<15 | half_bits(w)&0x7FFF

// ---------------- helpers ----------------------------------------------------
__device__ __forceinline__ void cp16(uint32_t s, const void* g) {
    asm volatile("cp.async.cg.shared.global [%0], [%1], 16;" :: "r"(s), "l"(g));
}
__device__ __forceinline__ uint32_t smem_u32(const void* p) {
    uint32_t a;
    asm("{ .reg .u64 t; cvta.to.shared.u64 t, %1; cvt.u32.u64 %0, t; }" : "=r"(a) : "l"(p));
    return a;
}
__device__ __forceinline__ void mma_f16(float* c, const uint32_t* a, const uint32_t* b) {
    asm volatile(
        "mma.sync.aligned.m16n8k16.row.col.f32.f16.f16.f32 "
        "{%0,%1,%2,%3}, {%4,%5,%6,%7}, {%8,%9}, {%0,%1,%2,%3};"
        : "+f"(c[0]), "+f"(c[1]), "+f"(c[2]), "+f"(c[3])
        : "r"(a[0]), "r"(a[1]), "r"(a[2]), "r"(a[3]), "r"(b[0]), "r"(b[1]));
}

// ---------------- prep kernels ----------------------------------------------
__global__ void k_prep0(const float* __restrict__ W1, const float* __restrict__ W2) {
    int i = blockIdx.x * blockDim.x + threadIdx.x;
    if (i < F_IN * F_H) {
        int k = i >> 7, n = i & 127;
        float v = W1[i];
        __half h = __float2half_rn(v);
        g_W1h[(size_t)n * F_IN + k] = h;
        g_W1l[(size_t)n * F_IN + k] = __float2half_rn(v - __half2float(h));
    }
    if (i < F_H * F_OUT) {
        int k = i / F_OUT, n = i % F_OUT;
        float v = W2[i];
        __half h = __float2half_rn(v);
        g_W2Th[(size_t)n * F_H + k] = h;
        g_W2Tl[(size_t)n * F_H + k] = __float2half_rn(v - __half2float(h));
    }
    if (i < N_NODES) g_cnt[i] = 0;
}
__global__ void k_count(const int* __restrict__ ei) {
    int e = blockIdx.x * blockDim.x + threadIdx.x;
    if (e < N_EDGES) atomicAdd(&g_cnt[ei[N_EDGES + e]], 1);
}
__global__ void k_scan1() {
    __shared__ int s[SCAN_B];
    int i = blockIdx.x * SCAN_B + threadIdx.x;
    int v = (i < N_NODES) ? g_cnt[i] : 0;
    if (i < N_NODES) {
        float d = (float)(v + 1);
        float r = rsqrtf(d);
        g_dinv[i]  = r;
        g_selfc[i] = (1.0f - ALPHA) * r * r;
    }
    s[threadIdx.x] = v;
    __syncthreads();
#pragma unroll
    for (int off = 1; off < SCAN_B; off <<= 1) {
        int t = (threadIdx.x >= off) ? s[threadIdx.x - off] : 0;
        __syncthreads();
        s[threadIdx.x] += t;
        __syncthreads();
    }
    if (i < N_NODES) g_offs[i] = s[threadIdx.x] - v;
    if (threadIdx.x == SCAN_B - 1) g_bsum[blockIdx.x] = s[SCAN_B - 1];
}
__global__ void k_scan2() {
    __shared__ int s[256];
    int t = threadIdx.x;
    int v = (t < NBLK) ? g_bsum[t] : 0;
    s[t] = v;
    __syncthreads();
#pragma unroll
    for (int off = 1; off < 256; off <<= 1) {
        int u = (t >= off) ? s[t - off] : 0;
        __syncthreads();
        s[t] += u;
        __syncthreads();
    }
    if (t < NBLK) g_bsum2[t] = s[t] - v;
    if (t == 0) g_offs[N_NODES] = s[255];
}
__global__ void k_scan3() {
    int i = blockIdx.x * blockDim.x + threadIdx.x;
    if (i >= N_NODES) return;
    int o = g_offs[i] + g_bsum2[i / SCAN_B];
    g_offs[i]   = o;
    g_cursor[i] = o;
}
__global__ void k_fill(const int* __restrict__ ei) {
    int e = blockIdx.x * blockDim.x + threadIdx.x;
    if (e >= N_EDGES) return;
    int r = ei[e];
    int c = ei[N_EDGES + e];
    int pos = atomicAdd(&g_cursor[c], 1);
    float w = (1.0f - ALPHA) * g_dinv[r] * g_dinv[c];
    uint32_t wb = (uint32_t)__half_as_ushort(__float2half_rn(w)) & 0x7FFFu;
    g_csr[pos] = ((uint32_t)r << 15) | wb;
}

// ---------------- GEMM1: h1 = fp16(relu(x @ W1 + b1)), fp16x3 MMA -----------
#define G1ST 40
__global__ void __launch_bounds__(256) k_gemm1(const float* __restrict__ x,
                                               const float* __restrict__ b1) {
    __shared__ __half xs_h[128 * G1ST], xs_l[128 * G1ST];
    __shared__ __half ws_h[128 * G1ST], ws_l[128 * G1ST];
    uint32_t wsh32 = smem_u32(ws_h), wsl32 = smem_u32(ws_l);

    int tid = threadIdx.x;
    int wid = tid >> 5, lid = tid & 31;
    int g = lid >> 2, tig = lid & 3;
    int wm = wid & 3, wn = wid >> 2;
    int row0 = blockIdx.x * 128;

    float acc[2][8][4];
#pragma unroll
    for (int mt = 0; mt < 2; mt++)
#pragma unroll
        for (int nt = 0; nt < 8; nt++)
#pragma unroll
            for (int i = 0; i < 4; i++) acc[mt][nt][i] = 0.0f;

    for (int kt = 0; kt < 16; kt++) {
#pragma unroll
        for (int i = 0; i < 2; i++) {
            int slot = tid + i * 256;
            int n = slot >> 2, c = slot & 3;
            cp16(wsh32 + (n * G1ST + c * 8) * 2, &g_W1h[(size_t)n * F_IN + kt * 32 + c * 8]);
            cp16(wsl32 + (n * G1ST + c * 8) * 2, &g_W1l[(size_t)n * F_IN + kt * 32 + c * 8]);
        }
        asm volatile("cp.async.commit_group;" ::: "memory");
#pragma unroll
        for (int i = 0; i < 4; i++) {
            int slot = tid + i * 256;
            int m = slot >> 3, c4 = slot & 7;
            int grow = row0 + m; if (grow >= N_NODES) grow = N_NODES - 1;
            float4 v = *(const float4*)&x[(size_t)grow * F_IN + kt * 32 + c4 * 4];
            __half hx0 = __float2half_rn(v.x), hx1 = __float2half_rn(v.y);
            __half hx2 = __float2half_rn(v.z), hx3 = __float2half_rn(v.w);
            __half lx0 = __float2half_rn(v.x - __half2float(hx0));
            __half lx1 = __float2half_rn(v.y - __half2float(hx1));
            __half lx2 = __float2half_rn(v.z - __half2float(hx2));
            __half lx3 = __float2half_rn(v.w - __half2float(hx3));
            __half* ph = &xs_h[m * G1ST + c4 * 4];
            __half* pl = &xs_l[m * G1ST + c4 * 4];
            *(__half2*)ph       = __halves2half2(hx0, hx1);
            *(__half2*)(ph + 2) = __halves2half2(hx2, hx3);
            *(__half2*)pl       = __halves2half2(lx0, lx1);
            *(__half2*)(pl + 2) = __halves2half2(lx2, lx3);
        }
        asm volatile("cp.async.wait_group 0;" ::: "memory");
        __syncthreads();

#pragma unroll
        for (int ks = 0; ks < 2; ks++) {
            int kk = ks * 16;
            uint32_t ah[2][4], al[2][4];
#pragma unroll
            for (int mt = 0; mt < 2; mt++) {
                int m = wm * 32 + mt * 16 + g;
                ah[mt][0] = *(uint32_t*)&xs_h[m * G1ST + kk + 2 * tig];
                ah[mt][1] = *(uint32_t*)&xs_h[(m + 8) * G1ST + kk + 2 * tig];
                ah[mt][2] = *(uint32_t*)&xs_h[m * G1ST + kk + 8 + 2 * tig];
                ah[mt][3] = *(uint32_t*)&xs_h[(m + 8) * G1ST + kk + 8 + 2 * tig];
                al[mt][0] = *(uint32_t*)&xs_l[m * G1ST + kk + 2 * tig];
                al[mt][1] = *(uint32_t*)&xs_l[(m + 8) * G1ST + kk + 2 * tig];
                al[mt][2] = *(uint32_t*)&xs_l[m * G1ST + kk + 8 + 2 * tig];
                al[mt][3] = *(uint32_t*)&xs_l[(m + 8) * G1ST + kk + 8 + 2 * tig];
            }
#pragma unroll
            for (int nt = 0; nt < 8; nt++) {
                int n = wn * 64 + nt * 8 + g;
                uint32_t bh[2], bl[2];
                bh[0] = *(uint32_t*)&ws_h[n * G1ST + kk + 2 * tig];
                bh[1] = *(uint32_t*)&ws_h[n * G1ST + kk + 8 + 2 * tig];
                bl[0] = *(uint32_t*)&ws_l[n * G1ST + kk + 2 * tig];
                bl[1] = *(uint32_t*)&ws_l[n * G1ST + kk + 8 + 2 * tig];
#pragma unroll
                for (int mt = 0; mt < 2; mt++) {
                    mma_f16(acc[mt][nt], ah[mt], bh);
                    mma_f16(acc[mt][nt], ah[mt], bl);
                    mma_f16(acc[mt][nt], al[mt], bh);
                }
            }
        }
        __syncthreads();
    }

#pragma unroll
    for (int nt = 0; nt < 8; nt++) {
        int col = wn * 64 + nt * 8 + tig * 2;
        float2 bb = *(const float2*)&b1[col];
#pragma unroll
        for (int mt = 0; mt < 2; mt++) {
            int r0 = row0 + wm * 32 + mt * 16 + g;
            if (r0 < N_NODES) {
                float ox = acc[mt][nt][0] + bb.x, oy = acc[mt][nt][1] + bb.y;
                ox = ox > 0.f ? ox : 0.f;  oy = oy > 0.f ? oy : 0.f;
                *(__half2*)&g_h1[(size_t)r0 * F_H + col] = __floats2half2_rn(ox, oy);
            }
            if (r0 + 8 < N_NODES) {
                float ox = acc[mt][nt][2] + bb.x, oy = acc[mt][nt][3] + bb.y;
                ox = ox > 0.f ? ox : 0.f;  oy = oy > 0.f ? oy : 0.f;
                *(__half2*)&g_h1[(size_t)(r0 + 8) * F_H + col] = __floats2half2_rn(ox, oy);
            }
        }
    }
}

// ---------------- GEMM2: h0h = fp16(relu(h1 @ W2 + b2)), fp16 MMA -----------
#define G2ST 136
#define G2SMEM ((128 * G2ST + 2 * F_OUT * G2ST) * 2)
__global__ void __launch_bounds__(256) k_gemm2(const float* __restrict__ b2) {
    extern __shared__ __half sm2[];
    __half* hs = sm2;
    __half* wh = sm2 + 128 * G2ST;
    __half* wl = wh + F_OUT * G2ST;
    uint32_t hs32 = smem_u32(hs), wh32 = smem_u32(wh), wl32 = smem_u32(wl);

    int tid = threadIdx.x;
    int wid = tid >> 5, lid = tid & 31;
    int g = lid >> 2, tig = lid & 3;
    int row0 = blockIdx.x * 128;

#pragma unroll
    for (int i = 0; i < 8; i++) {
        int slot = tid + i * 256;
        int m = slot >> 4, c = slot & 15;
        int grow = row0 + m; if (grow >= N_NODES) grow = N_NODES - 1;
        cp16(hs32 + (m * G2ST + c * 8) * 2, &g_h1[(size_t)grow * F_H + c * 8]);
    }
#pragma unroll
    for (int i = 0; i < 3; i++) {
        int slot = tid + i * 256;
        if (slot < F_OUT * 16) {
            int n = slot >> 4, c = slot & 15;
            cp16(wh32 + (n * G2ST + c * 8) * 2, &g_W2Th[(size_t)n * F_H + c * 8]);
            cp16(wl32 + (n * G2ST + c * 8) * 2, &g_W2Tl[(size_t)n * F_H + c * 8]);
        }
    }
    asm volatile("cp.async.commit_group;" ::: "memory");
    asm volatile("cp.async.wait_group 0;" ::: "memory");
    __syncthreads();

    float acc[5][4];
#pragma unroll
    for (int nt = 0; nt < 5; nt++)
#pragma unroll
        for (int i = 0; i < 4; i++) acc[nt][i] = 0.0f;

#pragma unroll
    for (int ks = 0; ks < 8; ks++) {
        int kk = ks * 16;
        int m = wid * 16 + g;
        uint32_t a[4];
        a[0] = *(uint32_t*)&hs[m * G2ST + kk + 2 * tig];
        a[1] = *(uint32_t*)&hs[(m + 8) * G2ST + kk + 2 * tig];
        a[2] = *(uint32_t*)&hs[m * G2ST + kk + 8 + 2 * tig];
        a[3] = *(uint32_t*)&hs[(m + 8) * G2ST + kk + 8 + 2 * tig];
#pragma unroll
        for (int nt = 0; nt < 5; nt++) {
            int n = nt * 8 + g;
            uint32_t bhv[2], blv[2];
            bhv[0] = *(uint32_t*)&wh[n * G2ST + kk + 2 * tig];
            bhv[1] = *(uint32_t*)&wh[n * G2ST + kk + 8 + 2 * tig];
            blv[0] = *(uint32_t*)&wl[n * G2ST + kk + 2 * tig];
            blv[1] = *(uint32_t*)&wl[n * G2ST + kk + 8 + 2 * tig];
            mma_f16(acc[nt], a, bhv);
            mma_f16(acc[nt], a, blv);
        }
    }

#pragma unroll
    for (int nt = 0; nt < 5; nt++) {
        int col = nt * 8 + tig * 2;
        float2 bb = *(const float2*)&b2[col];
        int r0 = row0 + wid * 16 + g;
        if (r0 < N_NODES) {
            float ox = acc[nt][0] + bb.x, oy = acc[nt][1] + bb.y;
            ox = ox > 0.f ? ox : 0.f;  oy = oy > 0.f ? oy : 0.f;
            *(__half2*)&g_h0h[(size_t)r0 * F_PAD + col] = __floats2half2_rn(ox, oy);
        }
        if (r0 + 8 < N_NODES) {
            float ox = acc[nt][2] + bb.x, oy = acc[nt][3] + bb.y;
            ox = ox > 0.f ? ox : 0.f;  oy = oy > 0.f ? oy : 0.f;
            *(__half2*)&g_h0h[(size_t)(r0 + 8) * F_PAD + col] = __floats2half2_rn(ox, oy);
        }
    }
}

// ---------------- propagation: warp-per-node pull (R9 layout), HFMA2 inner --
// 6 groups x 5 lanes; group handles edges e0+group+6k, unroll 4. Each 4-edge
// batch accumulates in half2 (HFMA2), then folds into fp32 accumulators:
// halves per-edge instruction count; batch rounding ~2^-12 relative.
#define NPW 8
template <bool LAST>
__global__ void __launch_bounds__(256) k_pull_w(const __half* __restrict__ srcp,
                                                void* __restrict__ dstv) {
    int lane = threadIdx.x & 31;
    int gw   = blockIdx.x * 8 + (threadIdx.x >> 5);
    int n0 = gw * NPW;
    if (n0 >= N_NODES) return;
    int n1 = n0 + NPW; if (n1 > N_NODES) n1 = N_NODES;

    const char* sbase = (const char*)srcp;
    const uint4* s4   = (const uint4*)srcp;
    const uint4* h4   = (const uint4*)g_h0h;
    int group = lane / 5;
    int q     = lane % 5;
    int qb    = q * 16;
    bool act  = lane < 30;

    for (int n = n0; n < n1; n++) {
        int e0 = g_offs[n], e1 = g_offs[n + 1];
        float2 acc[4];
#pragma unroll
        for (int j = 0; j < 4; j++) acc[j] = make_float2(0.f, 0.f);

        if (act) {
            int e = e0 + group;
            for (; e + 18 < e1; e += 24) {
                uint32_t p0 = __ldg(&g_csr[e]);
                uint32_t p1 = __ldg(&g_csr[e + 6]);
                uint32_t p2 = __ldg(&g_csr[e + 12]);
                uint32_t p3 = __ldg(&g_csr[e + 18]);
                uint4 r0 = __ldg((const uint4*)(sbase + ((p0 >> 8) & 0xFFFFFF80u) + qb));
                uint4 r1 = __ldg((const uint4*)(sbase + ((p1 >> 8) & 0xFFFFFF80u) + qb));
                uint4 r2 = __ldg((const uint4*)(sbase + ((p2 >> 8) & 0xFFFFFF80u) + qb));
                uint4 r3 = __ldg((const uint4*)(sbase + ((p3 >> 8) & 0xFFFFFF80u) + qb));
                __half2 w0 = __half2half2(__ushort_as_half((unsigned short)(p0 & 0x7FFFu)));
                __half2 w1 = __half2half2(__ushort_as_half((unsigned short)(p1 & 0x7FFFu)));
                __half2 w2 = __half2half2(__ushort_as_half((unsigned short)(p2 & 0x7FFFu)));
                __half2 w3 = __half2half2(__ushort_as_half((unsigned short)(p3 & 0x7FFFu)));
                const __half2* a0 = (const __half2*)&r0;
                const __half2* a1 = (const __half2*)&r1;
                const __half2* a2 = (const __half2*)&r2;
                const __half2* a3 = (const __half2*)&r3;
#pragma unroll
                for (int j = 0; j < 4; j++) {
                    __half2 hb = __hmul2(w0, a0[j]);
                    hb = __hfma2(w1, a1[j], hb);
                    hb = __hfma2(w2, a2[j], hb);
                    hb = __hfma2(w3, a3[j], hb);
                    float2 fb = __half22float2(hb);
                    acc[j].x += fb.x;
                    acc[j].y += fb.y;
                }
            }
            for (; e < e1; e += 6) {
                uint32_t p = __ldg(&g_csr[e]);
                uint4 r = __ldg((const uint4*)(sbase + ((p >> 8) & 0xFFFFFF80u) + qb));
                float w = __half2float(__ushort_as_half((unsigned short)(p & 0x7FFFu)));
                const __half2* a = (const __half2*)&r;
#pragma unroll
                for (int j = 0; j < 4; j++) {
                    float2 v = __half22float2(a[j]);
                    acc[j].x = fmaf(w, v.x, acc[j].x);
                    acc[j].y = fmaf(w, v.y, acc[j].y);
                }
            }
        }

        // reduce 6 groups: round1 (+15), then snapshot (+5, +10)
#pragma unroll
        for (int j = 0; j < 4; j++) {
            acc[j].x += __shfl_sync(0xFFFFFFFFu, acc[j].x, (lane + 15) & 31);
            acc[j].y += __shfl_sync(0xFFFFFFFFu, acc[j].y, (lane + 15) & 31);
        }
#pragma unroll
        for (int j = 0; j < 4; j++) {
            float tx1 = __shfl_sync(0xFFFFFFFFu, acc[j].x, (lane + 5) & 31);
            float ty1 = __shfl_sync(0xFFFFFFFFu, acc[j].y, (lane + 5) & 31);
            float tx2 = __shfl_sync(0xFFFFFFFFu, acc[j].x, (lane + 10) & 31);
            float ty2 = __shfl_sync(0xFFFFFFFFu, acc[j].y, (lane + 10) & 31);
            acc[j].x += tx1 + tx2;
            acc[j].y += ty1 + ty2;
        }

        if (lane < 5) {
            float sc = g_selfc[n];
            uint4 hraw = h4[n * 8 + lane];
            uint4 sraw = s4[n * 8 + lane];
            const __half2* hh = (const __half2*)&hraw;
            const __half2* sh = (const __half2*)&sraw;
#pragma unroll
            for (int j = 0; j < 4; j++) {
                float2 hv = __half22float2(hh[j]);
                float2 sv = __half22float2(sh[j]);
                acc[j].x += fmaf(sc, sv.x, ALPHA * hv.x);
                acc[j].y += fmaf(sc, sv.y, ALPHA * hv.y);
            }
            if (LAST) {
                float* out = (float*)dstv;
                float4 o0 = make_float4(acc[0].x, acc[0].y, acc[1].x, acc[1].y);
                float4 o1 = make_float4(acc[2].x, acc[2].y, acc[3].x, acc[3].y);
                *(float4*)&out[(size_t)n * F_OUT + lane * 8]     = o0;
                *(float4*)&out[(size_t)n * F_OUT + lane * 8 + 4] = o1;
            } else {
                uint4 o;
                __half2* oh = (__half2*)&o;
#pragma unroll
                for (int j = 0; j < 4; j++) oh[j] = __float22half2_rn(acc[j]);
                ((uint4*)dstv)[n * 8 + lane] = o;
            }
        }
    }
}

// ---------------- launcher ---------------------------------------------------
extern "C" void kernel_launch(void* const* d_in, const int* in_sizes, int n_in,
                              void* d_out, int out_size) {
    const float* x  = (const float*)d_in[0];
    const int*   ei = (const int*)  d_in[1];
    const float* W1 = (const float*)d_in[2];
    const float* b1 = (const float*)d_in[3];
    const float* W2 = (const float*)d_in[4];
    const float* b2 = (const float*)d_in[5];

    __half *zA, *zB, *h0h;
    cudaGetSymbolAddress((void**)&zA,  g_zhA);
    cudaGetSymbolAddress((void**)&zB,  g_zhB);
    cudaGetSymbolAddress((void**)&h0h, g_h0h);

    cudaFuncSetAttribute(k_gemm2, cudaFuncAttributeMaxDynamicSharedMemorySize, G2SMEM);

    // CSR build + weight prep
    k_prep0<<<(N_NODES + 255) / 256, 256>>>(W1, W2);
    k_count<<<(N_EDGES + 255) / 256, 256>>>(ei);
    k_scan1<<<NBLK, SCAN_B>>>();
    k_scan2<<<1, 256>>>();
    k_scan3<<<(N_NODES + 255) / 256, 256>>>();
    k_fill <<<(N_EDGES + 255) / 256, 256>>>(ei);

    // MLP encoder (fp16 tensor-core MMA)
    k_gemm1<<<(N_NODES + 127) / 128, 256>>>(x, b1);
    k_gemm2<<<(N_NODES + 127) / 128, 256, G2SMEM>>>(b2);

    // APPNP propagation (warp-per-node pull, fp16 z, packed CSR, HFMA2 inner)
    int nwarps = (N_NODES + NPW - 1) / NPW;
    int pgrid  = (nwarps + 7) / 8;
    const __half* src = h0h;
    for (int it = 0; it < K_ITERS - 1; it++) {
        __half* dst = (it & 1) ? zB : zA;
        k_pull_w<false><<<pgrid, 256>>>(src, dst);
        src = dst;
    }
    k_pull_w<true><<<pgrid, 256>>>(src, d_out);
}

// round 17
// speedup vs baseline: 1.1148x; 1.0401x over previous
#include <cuda_runtime.h>
#include <cuda_fp16.h>
#include <cstdint>

#define N_NODES 100000
#define N_EDGES 3200000
#define F_IN    512
#define F_H     128
#define F_OUT   40
#define F_PAD   64          // padded row length in halves (128 B rows)
#define K_ITERS 20
#define ALPHA   0.1f

#define SCAN_B  512
#define NBLK    ((N_NODES + SCAN_B - 1) / SCAN_B)   // 196

// ---------------- scratch (device globals; no runtime allocation) ----------
__device__ __half   g_h1[(size_t)N_NODES * F_H];
__device__ __half   g_W1h[(size_t)F_H * F_IN];
__device__ __half   g_W1l[(size_t)F_H * F_IN];
__device__ __half   g_W2Th[(size_t)F_OUT * F_H];
__device__ __half   g_W2Tl[(size_t)F_OUT * F_H];
__device__ __half   g_h0h[(size_t)N_NODES * F_PAD];   // padded 128B rows
__device__ __half   g_zhA[(size_t)N_NODES * F_PAD];
__device__ __half   g_zhB[(size_t)N_NODES * F_PAD];
__device__ int      g_cnt[N_NODES];
__device__ int      g_offs[N_NODES + 1];
__device__ int      g_cursor[N_NODES];
__device__ int      g_bsum[NBLK];
__device__ int      g_bsum2[NBLK];
__device__ float    g_dinv[N_NODES];
__device__ float    g_selfc[N_NODES];
__device__ uint32_t g_csr[N_EDGES];     // idx(17b)<<15 | half_bits(w)&0x7FFF

// ---------------- helpers ----------------------------------------------------
__device__ __forceinline__ void cp16(uint32_t s, const void* g) {
    asm volatile("cp.async.cg.shared.global [%0], [%1], 16;" :: "r"(s), "l"(g));
}
__device__ __forceinline__ uint32_t smem_u32(const void* p) {
    uint32_t a;
    asm("{ .reg .u64 t; cvta.to.shared.u64 t, %1; cvt.u32.u64 %0, t; }" : "=r"(a) : "l"(p));
    return a;
}
__device__ __forceinline__ void mma_f16(float* c, const uint32_t* a, const uint32_t* b) {
    asm volatile(
        "mma.sync.aligned.m16n8k16.row.col.f32.f16.f16.f32 "
        "{%0,%1,%2,%3}, {%4,%5,%6,%7}, {%8,%9}, {%0,%1,%2,%3};"
        : "+f"(c[0]), "+f"(c[1]), "+f"(c[2]), "+f"(c[3])
        : "r"(a[0]), "r"(a[1]), "r"(a[2]), "r"(a[3]), "r"(b[0]), "r"(b[1]));
}

// ---------------- prep kernels ----------------------------------------------
__global__ void k_prep0(const float* __restrict__ W1, const float* __restrict__ W2) {
    int i = blockIdx.x * blockDim.x + threadIdx.x;
    if (i < F_IN * F_H) {
        int k = i >> 7, n = i & 127;
        float v = W1[i];
        __half h = __float2half_rn(v);
        g_W1h[(size_t)n * F_IN + k] = h;
        g_W1l[(size_t)n * F_IN + k] = __float2half_rn(v - __half2float(h));
    }
    if (i < F_H * F_OUT) {
        int k = i / F_OUT, n = i % F_OUT;
        float v = W2[i];
        __half h = __float2half_rn(v);
        g_W2Th[(size_t)n * F_H + k] = h;
        g_W2Tl[(size_t)n * F_H + k] = __float2half_rn(v - __half2float(h));
    }
    if (i < N_NODES) g_cnt[i] = 0;
}
__global__ void k_count(const int* __restrict__ ei) {
    int e = blockIdx.x * blockDim.x + threadIdx.x;
    if (e < N_EDGES) atomicAdd(&g_cnt[ei[N_EDGES + e]], 1);
}
__global__ void k_scan1() {
    __shared__ int s[SCAN_B];
    int i = blockIdx.x * SCAN_B + threadIdx.x;
    int v = (i < N_NODES) ? g_cnt[i] : 0;
    if (i < N_NODES) {
        float d = (float)(v + 1);
        float r = rsqrtf(d);
        g_dinv[i]  = r;
        g_selfc[i] = (1.0f - ALPHA) * r * r;
    }
    s[threadIdx.x] = v;
    __syncthreads();
#pragma unroll
    for (int off = 1; off < SCAN_B; off <<= 1) {
        int t = (threadIdx.x >= off) ? s[threadIdx.x - off] : 0;
        __syncthreads();
        s[threadIdx.x] += t;
        __syncthreads();
    }
    if (i < N_NODES) g_offs[i] = s[threadIdx.x] - v;
    if (threadIdx.x == SCAN_B - 1) g_bsum[blockIdx.x] = s[SCAN_B - 1];
}
__global__ void k_scan2() {
    __shared__ int s[256];
    int t = threadIdx.x;
    int v = (t < NBLK) ? g_bsum[t] : 0;
    s[t] = v;
    __syncthreads();
#pragma unroll
    for (int off = 1; off < 256; off <<= 1) {
        int u = (t >= off) ? s[t - off] : 0;
        __syncthreads();
        s[t] += u;
        __syncthreads();
    }
    if (t < NBLK) g_bsum2[t] = s[t] - v;
    if (t == 0) g_offs[N_NODES] = s[255];
}
__global__ void k_scan3() {
    int i = blockIdx.x * blockDim.x + threadIdx.x;
    if (i >= N_NODES) return;
    int o = g_offs[i] + g_bsum2[i / SCAN_B];
    g_offs[i]   = o;
    g_cursor[i] = o;
}
__global__ void k_fill(const int* __restrict__ ei) {
    int e = blockIdx.x * blockDim.x + threadIdx.x;
    if (e >= N_EDGES) return;
    int r = ei[e];
    int c = ei[N_EDGES + e];
    int pos = atomicAdd(&g_cursor[c], 1);
    float w = (1.0f - ALPHA) * g_dinv[r] * g_dinv[c];
    uint32_t wb = (uint32_t)__half_as_ushort(__float2half_rn(w)) & 0x7FFFu;
    g_csr[pos] = ((uint32_t)r << 15) | wb;
}

// ---------------- GEMM1: h1 = fp16(relu(x @ W1 + b1)), fp16x3 MMA -----------
#define G1ST 40
__global__ void __launch_bounds__(256) k_gemm1(const float* __restrict__ x,
                                               const float* __restrict__ b1) {
    __shared__ __half xs_h[128 * G1ST], xs_l[128 * G1ST];
    __shared__ __half ws_h[128 * G1ST], ws_l[128 * G1ST];
    uint32_t wsh32 = smem_u32(ws_h), wsl32 = smem_u32(ws_l);

    int tid = threadIdx.x;
    int wid = tid >> 5, lid = tid & 31;
    int g = lid >> 2, tig = lid & 3;
    int wm = wid & 3, wn = wid >> 2;
    int row0 = blockIdx.x * 128;

    float acc[2][8][4];
#pragma unroll
    for (int mt = 0; mt < 2; mt++)
#pragma unroll
        for (int nt = 0; nt < 8; nt++)
#pragma unroll
            for (int i = 0; i < 4; i++) acc[mt][nt][i] = 0.0f;

    for (int kt = 0; kt < 16; kt++) {
#pragma unroll
        for (int i = 0; i < 2; i++) {
            int slot = tid + i * 256;
            int n = slot >> 2, c = slot & 3;
            cp16(wsh32 + (n * G1ST + c * 8) * 2, &g_W1h[(size_t)n * F_IN + kt * 32 + c * 8]);
            cp16(wsl32 + (n * G1ST + c * 8) * 2, &g_W1l[(size_t)n * F_IN + kt * 32 + c * 8]);
        }
        asm volatile("cp.async.commit_group;" ::: "memory");
#pragma unroll
        for (int i = 0; i < 4; i++) {
            int slot = tid + i * 256;
            int m = slot >> 3, c4 = slot & 7;
            int grow = row0 + m; if (grow >= N_NODES) grow = N_NODES - 1;
            float4 v = *(const float4*)&x[(size_t)grow * F_IN + kt * 32 + c4 * 4];
            __half hx0 = __float2half_rn(v.x), hx1 = __float2half_rn(v.y);
            __half hx2 = __float2half_rn(v.z), hx3 = __float2half_rn(v.w);
            __half lx0 = __float2half_rn(v.x - __half2float(hx0));
            __half lx1 = __float2half_rn(v.y - __half2float(hx1));
            __half lx2 = __float2half_rn(v.z - __half2float(hx2));
            __half lx3 = __float2half_rn(v.w - __half2float(hx3));
            __half* ph = &xs_h[m * G1ST + c4 * 4];
            __half* pl = &xs_l[m * G1ST + c4 * 4];
            *(__half2*)ph       = __halves2half2(hx0, hx1);
            *(__half2*)(ph + 2) = __halves2half2(hx2, hx3);
            *(__half2*)pl       = __halves2half2(lx0, lx1);
            *(__half2*)(pl + 2) = __halves2half2(lx2, lx3);
        }
        asm volatile("cp.async.wait_group 0;" ::: "memory");
        __syncthreads();

#pragma unroll
        for (int ks = 0; ks < 2; ks++) {
            int kk = ks * 16;
            uint32_t ah[2][4], al[2][4];
#pragma unroll
            for (int mt = 0; mt < 2; mt++) {
                int m = wm * 32 + mt * 16 + g;
                ah[mt][0] = *(uint32_t*)&xs_h[m * G1ST + kk + 2 * tig];
                ah[mt][1] = *(uint32_t*)&xs_h[(m + 8) * G1ST + kk + 2 * tig];
                ah[mt][2] = *(uint32_t*)&xs_h[m * G1ST + kk + 8 + 2 * tig];
                ah[mt][3] = *(uint32_t*)&xs_h[(m + 8) * G1ST + kk + 8 + 2 * tig];
                al[mt][0] = *(uint32_t*)&xs_l[m * G1ST + kk + 2 * tig];
                al[mt][1] = *(uint32_t*)&xs_l[(m + 8) * G1ST + kk + 2 * tig];
                al[mt][2] = *(uint32_t*)&xs_l[m * G1ST + kk + 8 + 2 * tig];
                al[mt][3] = *(uint32_t*)&xs_l[(m + 8) * G1ST + kk + 8 + 2 * tig];
            }
#pragma unroll
            for (int nt = 0; nt < 8; nt++) {
                int n = wn * 64 + nt * 8 + g;
                uint32_t bh[2], bl[2];
                bh[0] = *(uint32_t*)&ws_h[n * G1ST + kk + 2 * tig];
                bh[1] = *(uint32_t*)&ws_h[n * G1ST + kk + 8 + 2 * tig];
                bl[0] = *(uint32_t*)&ws_l[n * G1ST + kk + 2 * tig];
                bl[1] = *(uint32_t*)&ws_l[n * G1ST + kk + 8 + 2 * tig];
#pragma unroll
                for (int mt = 0; mt < 2; mt++) {
                    mma_f16(acc[mt][nt], ah[mt], bh);
                    mma_f16(acc[mt][nt], ah[mt], bl);
                    mma_f16(acc[mt][nt], al[mt], bh);
                }
            }
        }
        __syncthreads();
    }

#pragma unroll
    for (int nt = 0; nt < 8; nt++) {
        int col = wn * 64 + nt * 8 + tig * 2;
        float2 bb = *(const float2*)&b1[col];
#pragma unroll
        for (int mt = 0; mt < 2; mt++) {
            int r0 = row0 + wm * 32 + mt * 16 + g;
            if (r0 < N_NODES) {
                float ox = acc[mt][nt][0] + bb.x, oy = acc[mt][nt][1] + bb.y;
                ox = ox > 0.f ? ox : 0.f;  oy = oy > 0.f ? oy : 0.f;
                *(__half2*)&g_h1[(size_t)r0 * F_H + col] = __floats2half2_rn(ox, oy);
            }
            if (r0 + 8 < N_NODES) {
                float ox = acc[mt][nt][2] + bb.x, oy = acc[mt][nt][3] + bb.y;
                ox = ox > 0.f ? ox : 0.f;  oy = oy > 0.f ? oy : 0.f;
                *(__half2*)&g_h1[(size_t)(r0 + 8) * F_H + col] = __floats2half2_rn(ox, oy);
            }
        }
    }
}

// ---------------- GEMM2: h0h = fp16(relu(h1 @ W2 + b2)), fp16 MMA -----------
#define G2ST 136
#define G2SMEM ((128 * G2ST + 2 * F_OUT * G2ST) * 2)
__global__ void __launch_bounds__(256) k_gemm2(const float* __restrict__ b2) {
    extern __shared__ __half sm2[];
    __half* hs = sm2;
    __half* wh = sm2 + 128 * G2ST;
    __half* wl = wh + F_OUT * G2ST;
    uint32_t hs32 = smem_u32(hs), wh32 = smem_u32(wh), wl32 = smem_u32(wl);

    int tid = threadIdx.x;
    int wid = tid >> 5, lid = tid & 31;
    int g = lid >> 2, tig = lid & 3;
    int row0 = blockIdx.x * 128;

#pragma unroll
    for (int i = 0; i < 8; i++) {
        int slot = tid + i * 256;
        int m = slot >> 4, c = slot & 15;
        int grow = row0 + m; if (grow >= N_NODES) grow = N_NODES - 1;
        cp16(hs32 + (m * G2ST + c * 8) * 2, &g_h1[(size_t)grow * F_H + c * 8]);
    }
#pragma unroll
    for (int i = 0; i < 3; i++) {
        int slot = tid + i * 256;
        if (slot < F_OUT * 16) {
            int n = slot >> 4, c = slot & 15;
            cp16(wh32 + (n * G2ST + c * 8) * 2, &g_W2Th[(size_t)n * F_H + c * 8]);
            cp16(wl32 + (n * G2ST + c * 8) * 2, &g_W2Tl[(size_t)n * F_H + c * 8]);
        }
    }
    asm volatile("cp.async.commit_group;" ::: "memory");
    asm volatile("cp.async.wait_group 0;" ::: "memory");
    __syncthreads();

    float acc[5][4];
#pragma unroll
    for (int nt = 0; nt < 5; nt++)
#pragma unroll
        for (int i = 0; i < 4; i++) acc[nt][i] = 0.0f;

#pragma unroll
    for (int ks = 0; ks < 8; ks++) {
        int kk = ks * 16;
        int m = wid * 16 + g;
        uint32_t a[4];
        a[0] = *(uint32_t*)&hs[m * G2ST + kk + 2 * tig];
        a[1] = *(uint32_t*)&hs[(m + 8) * G2ST + kk + 2 * tig];
        a[2] = *(uint32_t*)&hs[m * G2ST + kk + 8 + 2 * tig];
        a[3] = *(uint32_t*)&hs[(m + 8) * G2ST + kk + 8 + 2 * tig];
#pragma unroll
        for (int nt = 0; nt < 5; nt++) {
            int n = nt * 8 + g;
            uint32_t bhv[2], blv[2];
            bhv[0] = *(uint32_t*)&wh[n * G2ST + kk + 2 * tig];
            bhv[1] = *(uint32_t*)&wh[n * G2ST + kk + 8 + 2 * tig];
            blv[0] = *(uint32_t*)&wl[n * G2ST + kk + 2 * tig];
            blv[1] = *(uint32_t*)&wl[n * G2ST + kk + 8 + 2 * tig];
            mma_f16(acc[nt], a, bhv);
            mma_f16(acc[nt], a, blv);
        }
    }

#pragma unroll
    for (int nt = 0; nt < 5; nt++) {
        int col = nt * 8 + tig * 2;
        float2 bb = *(const float2*)&b2[col];
        int r0 = row0 + wid * 16 + g;
        if (r0 < N_NODES) {
            float ox = acc[nt][0] + bb.x, oy = acc[nt][1] + bb.y;
            ox = ox > 0.f ? ox : 0.f;  oy = oy > 0.f ? oy : 0.f;
            *(__half2*)&g_h0h[(size_t)r0 * F_PAD + col] = __floats2half2_rn(ox, oy);
        }
        if (r0 + 8 < N_NODES) {
            float ox = acc[nt][2] + bb.x, oy = acc[nt][3] + bb.y;
            ox = ox > 0.f ? ox : 0.f;  oy = oy > 0.f ? oy : 0.f;
            *(__half2*)&g_h0h[(size_t)(r0 + 8) * F_PAD + col] = __floats2half2_rn(ox, oy);
        }
    }
}

// ---------------- propagation: warp-per-node pull, HFMA2 batch + HFMA2 tail -
#define NPW 8
template <bool LAST>
__global__ void __launch_bounds__(256) k_pull_w(const __half* __restrict__ srcp,
                                                void* __restrict__ dstv) {
    int lane = threadIdx.x & 31;
    int gw   = blockIdx.x * 8 + (threadIdx.x >> 5);
    int n0 = gw * NPW;
    if (n0 >= N_NODES) return;
    int n1 = n0 + NPW; if (n1 > N_NODES) n1 = N_NODES;

    const char* sbase = (const char*)srcp;
    const uint4* s4   = (const uint4*)srcp;
    const uint4* h4   = (const uint4*)g_h0h;
    int group = lane / 5;
    int q     = lane % 5;
    int qb    = q * 16;
    bool act  = lane < 30;

    for (int n = n0; n < n1; n++) {
        int e0 = g_offs[n], e1 = g_offs[n + 1];
        float2 acc[4];
#pragma unroll
        for (int j = 0; j < 4; j++) acc[j] = make_float2(0.f, 0.f);

        if (act) {
            int e = e0 + group;
            for (; e + 18 < e1; e += 24) {
                uint32_t p0 = __ldg(&g_csr[e]);
                uint32_t p1 = __ldg(&g_csr[e + 6]);
                uint32_t p2 = __ldg(&g_csr[e + 12]);
                uint32_t p3 = __ldg(&g_csr[e + 18]);
                uint4 r0 = __ldg((const uint4*)(sbase + ((p0 >> 8) & 0xFFFFFF80u) + qb));
                uint4 r1 = __ldg((const uint4*)(sbase + ((p1 >> 8) & 0xFFFFFF80u) + qb));
                uint4 r2 = __ldg((const uint4*)(sbase + ((p2 >> 8) & 0xFFFFFF80u) + qb));
                uint4 r3 = __ldg((const uint4*)(sbase + ((p3 >> 8) & 0xFFFFFF80u) + qb));
                __half2 w0 = __half2half2(__ushort_as_half((unsigned short)(p0 & 0x7FFFu)));
                __half2 w1 = __half2half2(__ushort_as_half((unsigned short)(p1 & 0x7FFFu)));
                __half2 w2 = __half2half2(__ushort_as_half((unsigned short)(p2 & 0x7FFFu)));
                __half2 w3 = __half2half2(__ushort_as_half((unsigned short)(p3 & 0x7FFFu)));
                const __half2* a0 = (const __half2*)&r0;
                const __half2* a1 = (const __half2*)&r1;
                const __half2* a2 = (const __half2*)&r2;
                const __half2* a3 = (const __half2*)&r3;
#pragma unroll
                for (int j = 0; j < 4; j++) {
                    __half2 hb = __hmul2(w0, a0[j]);
                    hb = __hfma2(w1, a1[j], hb);
                    hb = __hfma2(w2, a2[j], hb);
                    hb = __hfma2(w3, a3[j], hb);
                    float2 fb = __half22float2(hb);
                    acc[j].x += fb.x;
                    acc[j].y += fb.y;
                }
            }
            // HFMA2 tail: accumulate singles in half2, fold once
            __half2 ht[4];
#pragma unroll
            for (int j = 0; j < 4; j++) ht[j] = __half2half2(__ushort_as_half(0));
            for (; e < e1; e += 6) {
                uint32_t p = __ldg(&g_csr[e]);
                uint4 r = __ldg((const uint4*)(sbase + ((p >> 8) & 0xFFFFFF80u) + qb));
                __half2 w = __half2half2(__ushort_as_half((unsigned short)(p & 0x7FFFu)));
                const __half2* a = (const __half2*)&r;
#pragma unroll
                for (int j = 0; j < 4; j++) ht[j] = __hfma2(w, a[j], ht[j]);
            }
#pragma unroll
            for (int j = 0; j < 4; j++) {
                float2 fb = __half22float2(ht[j]);
                acc[j].x += fb.x;
                acc[j].y += fb.y;
            }
        }

        // reduce 6 groups: round1 (+15), then snapshot (+5, +10)
#pragma unroll
        for (int j = 0; j < 4; j++) {
            acc[j].x += __shfl_sync(0xFFFFFFFFu, acc[j].x, (lane + 15) & 31);
            acc[j].y += __shfl_sync(0xFFFFFFFFu, acc[j].y, (lane + 15) & 31);
        }
#pragma unroll
        for (int j = 0; j < 4; j++) {
            float tx1 = __shfl_sync(0xFFFFFFFFu, acc[j].x, (lane + 5) & 31);
            float ty1 = __shfl_sync(0xFFFFFFFFu, acc[j].y, (lane + 5) & 31);
            float tx2 = __shfl_sync(0xFFFFFFFFu, acc[j].x, (lane + 10) & 31);
            float ty2 = __shfl_sync(0xFFFFFFFFu, acc[j].y, (lane + 10) & 31);
            acc[j].x += tx1 + tx2;
            acc[j].y += ty1 + ty2;
        }

        if (lane < 5) {
            float sc = g_selfc[n];
            uint4 hraw = h4[n * 8 + lane];
            uint4 sraw = s4[n * 8 + lane];
            const __half2* hh = (const __half2*)&hraw;
            const __half2* sh = (const __half2*)&sraw;
#pragma unroll
            for (int j = 0; j < 4; j++) {
                float2 hv = __half22float2(hh[j]);
                float2 sv = __half22float2(sh[j]);
                acc[j].x += fmaf(sc, sv.x, ALPHA * hv.x);
                acc[j].y += fmaf(sc, sv.y, ALPHA * hv.y);
            }
            if (LAST) {
                float* out = (float*)dstv;
                float4 o0 = make_float4(acc[0].x, acc[0].y, acc[1].x, acc[1].y);
                float4 o1 = make_float4(acc[2].x, acc[2].y, acc[3].x, acc[3].y);
                *(float4*)&out[(size_t)n * F_OUT + lane * 8]     = o0;
                *(float4*)&out[(size_t)n * F_OUT + lane * 8 + 4] = o1;
            } else {
                uint4 o;
                __half2* oh = (__half2*)&o;
#pragma unroll
                for (int j = 0; j < 4; j++) oh[j] = __float22half2_rn(acc[j]);
                ((uint4*)dstv)[n * 8 + lane] = o;
            }
        }
    }
}

// ---------------- launcher ---------------------------------------------------
extern "C" void kernel_launch(void* const* d_in, const int* in_sizes, int n_in,
                              void* d_out, int out_size) {
    const float* x  = (const float*)d_in[0];
    const int*   ei = (const int*)  d_in[1];
    const float* W1 = (const float*)d_in[2];
    const float* b1 = (const float*)d_in[3];
    const float* W2 = (const float*)d_in[4];
    const float* b2 = (const float*)d_in[5];

    __half *zA, *zB, *h0h;
    cudaGetSymbolAddress((void**)&zA,  g_zhA);
    cudaGetSymbolAddress((void**)&zB,  g_zhB);
    cudaGetSymbolAddress((void**)&h0h, g_h0h);

    cudaFuncSetAttribute(k_gemm2, cudaFuncAttributeMaxDynamicSharedMemorySize, G2SMEM);

    // Forked-stream overlap: CSR build (default stream) || MLP (s1).
    cudaStream_t s1;
    cudaEvent_t  evFork, evJoin;
    cudaStreamCreateWithFlags(&s1, cudaStreamNonBlocking);
    cudaEventCreateWithFlags(&evFork, cudaEventDisableTiming);
    cudaEventCreateWithFlags(&evJoin, cudaEventDisableTiming);

    // common prologue (weights split + cnt zero)
    k_prep0<<<(N_NODES + 255) / 256, 256>>>(W1, W2);
    cudaEventRecord(evFork, 0);
    cudaStreamWaitEvent(s1, evFork, 0);

    // branch A (s1): MLP encoder
    k_gemm1<<<(N_NODES + 127) / 128, 256, 0, s1>>>(x, b1);
    k_gemm2<<<(N_NODES + 127) / 128, 256, G2SMEM, s1>>>(b2);
    cudaEventRecord(evJoin, s1);

    // branch B (default): CSR build
    k_count<<<(N_EDGES + 255) / 256, 256>>>(ei);
    k_scan1<<<NBLK, SCAN_B>>>();
    k_scan2<<<1, 256>>>();
    k_scan3<<<(N_NODES + 255) / 256, 256>>>();
    k_fill <<<(N_EDGES + 255) / 256, 256>>>(ei);

    // join
    cudaStreamWaitEvent(0, evJoin, 0);

    // APPNP propagation (warp-per-node pull, fp16 z, packed CSR, HFMA2)
    int nwarps = (N_NODES + NPW - 1) / NPW;
    int pgrid  = (nwarps + 7) / 8;
    const __half* src = h0h;
    for (int it = 0; it < K_ITERS - 1; it++) {
        __half* dst = (it & 1) ? zB : zA;
        k_pull_w<false><<<pgrid, 256>>>(src, dst);
        src = dst;
    }
    k_pull_w<true><<<pgrid, 256>>>(src, d_out);
}